// round 5
// baseline (speedup 1.0000x reference)
#include <cuda_runtime.h>
#include <cstdint>

// Problem constants
#define BATCH       16384
#define FEAT_DIM    512
#define NUM_CLASSES 100000
#define ALPHA       0.5f
#define LAMDA       0.003f

#define D4 (FEAT_DIM / 4)   // 128 float4 per row

// Scratch: per-class counts (zeroed every launch; graph-replay safe)
__device__ int g_counts[NUM_CLASSES];

// ---------------------------------------------------------------------------
// Kernel 1: zero the counts array
// ---------------------------------------------------------------------------
__global__ void zero_counts_kernel() {
    int i = blockIdx.x * blockDim.x + threadIdx.x;
    if (i < NUM_CLASSES) g_counts[i] = 0;
}

// ---------------------------------------------------------------------------
// Kernel 2: histogram targets
// ---------------------------------------------------------------------------
__global__ void count_kernel(const int* __restrict__ targets) {
    int i = blockIdx.x * blockDim.x + threadIdx.x;
    if (i < BATCH) atomicAdd(&g_counts[targets[i]], 1);
}

// ---------------------------------------------------------------------------
// Kernel 3: bulk copy centers -> new_centers (float4, grid-stride)
// ---------------------------------------------------------------------------
__global__ void copy_centers_kernel(const float4* __restrict__ src,
                                    float4* __restrict__ dst) {
    const long long n = (long long)NUM_CLASSES * D4;   // 12.8M float4
    long long i = (long long)blockIdx.x * blockDim.x + threadIdx.x;
    long long stride = (long long)gridDim.x * blockDim.x;
    for (; i < n; i += stride) dst[i] = src[i];
}

// ---------------------------------------------------------------------------
// Kernel 4: fused per-sample — loss, target_weights, scatter center-delta
//   grid = BATCH, block = 128 (one float4 per thread)
// ---------------------------------------------------------------------------
__global__ void fused_kernel(const float4* __restrict__ inputs4,
                             const float4* __restrict__ centers4,
                             const float*  __restrict__ wpc,
                             const int*    __restrict__ targets,
                             float4* __restrict__ loss4,
                             float4* __restrict__ tw4,
                             float*  __restrict__ out_centers) {
    const int b = blockIdx.x;
    const int t = threadIdx.x;          // 0..127

    const int cls = targets[b];
    const float cnt   = (float)g_counts[cls];
    const float scale = -ALPHA / (1.0f + cnt);          // per-sample contribution
    const float twv   = LAMDA * __ldg(&wpc[cls]);

    const long long in_idx  = (long long)b * D4 + t;
    const long long cen_idx = (long long)cls * D4 + t;

    const float4 x = inputs4[in_idx];
    const float4 c = centers4[cen_idx];

    float4 d;
    d.x = x.x - c.x; d.y = x.y - c.y; d.z = x.z - c.z; d.w = x.w - c.w;

    float4 l;
    l.x = 0.5f * d.x * d.x;
    l.y = 0.5f * d.y * d.y;
    l.z = 0.5f * d.z * d.z;
    l.w = 0.5f * d.w * d.w;

    loss4[in_idx] = l;
    tw4[in_idx]   = make_float4(twv, twv, twv, twv);

    // scatter: new_centers[cls, t*4 + k] += x.k * scale  (REDG, no return)
    float* base = out_centers + (long long)cls * FEAT_DIM + t * 4;
    atomicAdd(base + 0, x.x * scale);
    atomicAdd(base + 1, x.y * scale);
    atomicAdd(base + 2, x.z * scale);
    atomicAdd(base + 3, x.w * scale);
}

// ---------------------------------------------------------------------------
// Launch
// ---------------------------------------------------------------------------
extern "C" void kernel_launch(void* const* d_in, const int* in_sizes, int n_in,
                              void* d_out, int out_size) {
    const float* inputs  = (const float*)d_in[0];   // [B, D]
    const float* centers = (const float*)d_in[1];   // [C, D]
    const float* wpc     = (const float*)d_in[2];   // [C]
    const int*   targets = (const int*)d_in[3];     // [B]

    float* out = (float*)d_out;
    float* out_loss    = out;                                           // [B, D]
    float* out_tw      = out + (long long)BATCH * FEAT_DIM;             // [B, D]
    float* out_centers = out + 2LL * BATCH * FEAT_DIM;                  // [C, D]

    // 1) zero counts
    zero_counts_kernel<<<(NUM_CLASSES + 255) / 256, 256>>>();

    // 2) histogram targets
    count_kernel<<<(BATCH + 255) / 256, 256>>>(targets);

    // 3) copy centers -> new_centers
    {
        const int threads = 256;
        const int blocks  = 148 * 16;   // grid-stride, full-chip
        copy_centers_kernel<<<blocks, threads>>>((const float4*)centers,
                                                 (float4*)out_centers);
    }

    // 4) fused loss + weights + scatter delta
    fused_kernel<<<BATCH, 128>>>((const float4*)inputs,
                                 (const float4*)centers,
                                 wpc, targets,
                                 (float4*)out_loss,
                                 (float4*)out_tw,
                                 out_centers);
}

// round 8
// speedup vs baseline: 1.0589x; 1.0589x over previous
#include <cuda_runtime.h>
#include <cstdint>

// Problem constants
#define BATCH       16384
#define FEAT_DIM    512
#define NUM_CLASSES 100000
#define ALPHA       0.5f
#define LAMDA       0.003f

#define D4 (FEAT_DIM / 4)        // 128 float4 per row

// Mega-kernel geometry: every 7th block is a "fused" (per-sample) block,
// the other 6/7 are "copy" (per-class) blocks.
// TOTAL_BLOCKS - ceil(TOTAL_BLOCKS/7) == NUM_CLASSES exactly.
#define TOTAL_BLOCKS 116667      // 16667 fused-slots (16384 used) + 100000 copy

// Scratch: per-class counts (zeroed every launch; graph-replay safe)
__device__ int g_counts[NUM_CLASSES];

// ---------------------------------------------------------------------------
// vector red helper: one 16B relaxed add per lane
// ---------------------------------------------------------------------------
__device__ __forceinline__ void red_add_v4(float* p, float4 v) {
    asm volatile("red.global.add.v4.f32 [%0], {%1, %2, %3, %4};"
                 :: "l"(p), "f"(v.x), "f"(v.y), "f"(v.z), "f"(v.w)
                 : "memory");
}

// ---------------------------------------------------------------------------
// Kernel 1: zero the counts array
// ---------------------------------------------------------------------------
__global__ void zero_counts_kernel() {
    int i = blockIdx.x * blockDim.x + threadIdx.x;
    if (i < NUM_CLASSES) g_counts[i] = 0;
}

// ---------------------------------------------------------------------------
// Kernel 2: histogram targets
// ---------------------------------------------------------------------------
__global__ void count_kernel(const int* __restrict__ targets) {
    int i = blockIdx.x * blockDim.x + threadIdx.x;
    if (i < BATCH) atomicAdd(&g_counts[targets[i]], 1);
}

// ---------------------------------------------------------------------------
// Kernel 3: zero the touched rows of out_centers (one warp per class row)
//   ~15K touched rows expected -> ~30 MB of stores
// ---------------------------------------------------------------------------
__global__ void zero_touched_kernel(float* __restrict__ out_centers) {
    int r = blockIdx.x * 8 + (threadIdx.x >> 5);
    if (r >= NUM_CLASSES) return;
    if (g_counts[r] == 0) return;
    int lane = threadIdx.x & 31;
    float4* dst = (float4*)(out_centers + (long long)r * FEAT_DIM);
    const float4 z = make_float4(0.f, 0.f, 0.f, 0.f);
#pragma unroll
    for (int i = 0; i < 4; i++) dst[lane + 32 * i] = z;
}

// ---------------------------------------------------------------------------
// Kernel 4 (mega): concurrent copy-merge + per-sample fused work.
//   block = 128 threads (one float4 lane per thread of a 512-float row)
//   blockIdx % 7 == 0  -> fused block for sample b = blockIdx/7
//   else               -> copy block for class c = blockIdx - blockIdx/7 - 1
// Touched rows were pre-zeroed, so both roles contribute via commutative
// red.add and can interleave freely within one kernel.
// ---------------------------------------------------------------------------
__global__ void __launch_bounds__(128) mega_kernel(
        const float4* __restrict__ inputs4,
        const float4* __restrict__ centers4,
        const float*  __restrict__ wpc,
        const int*    __restrict__ targets,
        float4* __restrict__ loss4,
        float4* __restrict__ tw4,
        float*  __restrict__ out_centers) {
    const int k = blockIdx.x;
    const int t = threadIdx.x;          // 0..127
    const int q = k / 7;

    if (k - q * 7 == 0) {
        // ---------------- fused per-sample block ----------------
        const int b = q;
        if (b >= BATCH) return;

        const int   cls   = targets[b];
        const float cnt   = (float)g_counts[cls];
        const float scale = -ALPHA / (1.0f + cnt);
        const float twv   = LAMDA * __ldg(&wpc[cls]);

        const long long in_idx  = (long long)b * D4 + t;
        const long long cen_idx = (long long)cls * D4 + t;

        const float4 x = __ldcs(&inputs4[in_idx]);
        const float4 c = __ldg(&centers4[cen_idx]);

        float4 d;
        d.x = x.x - c.x; d.y = x.y - c.y; d.z = x.z - c.z; d.w = x.w - c.w;

        float4 l;
        l.x = 0.5f * d.x * d.x;
        l.y = 0.5f * d.y * d.y;
        l.z = 0.5f * d.z * d.z;
        l.w = 0.5f * d.w * d.w;

        __stcs(&loss4[in_idx], l);
        __stcs(&tw4[in_idx], make_float4(twv, twv, twv, twv));

        float* base = out_centers + (long long)cls * FEAT_DIM + t * 4;
        red_add_v4(base, make_float4(x.x * scale, x.y * scale,
                                     x.z * scale, x.w * scale));
    } else {
        // ---------------- copy / merge block for one class row ----------------
        const int c = k - q - 1;        // 0 .. NUM_CLASSES-1 exactly

        const long long idx = (long long)c * D4 + t;
        const float4 v = __ldcs(&centers4[idx]);

        if (g_counts[c] == 0) {
            __stcs((float4*)(out_centers) + idx, v);
        } else {
            red_add_v4(out_centers + (long long)c * FEAT_DIM + t * 4, v);
        }
    }
}

// ---------------------------------------------------------------------------
// Launch
// ---------------------------------------------------------------------------
extern "C" void kernel_launch(void* const* d_in, const int* in_sizes, int n_in,
                              void* d_out, int out_size) {
    const float* inputs  = (const float*)d_in[0];   // [B, D]
    const float* centers = (const float*)d_in[1];   // [C, D]
    const float* wpc     = (const float*)d_in[2];   // [C]
    const int*   targets = (const int*)d_in[3];     // [B]

    float* out = (float*)d_out;
    float* out_loss    = out;                                   // [B, D]
    float* out_tw      = out + (long long)BATCH * FEAT_DIM;     // [B, D]
    float* out_centers = out + 2LL * BATCH * FEAT_DIM;          // [C, D]

    // 1) zero counts
    zero_counts_kernel<<<(NUM_CLASSES + 255) / 256, 256>>>();

    // 2) histogram targets
    count_kernel<<<(BATCH + 255) / 256, 256>>>(targets);

    // 3) zero the touched rows of out_centers
    zero_touched_kernel<<<(NUM_CLASSES + 7) / 8, 256>>>(out_centers);

    // 4) mega: concurrent copy-merge + fused loss/tw/scatter
    mega_kernel<<<TOTAL_BLOCKS, 128>>>((const float4*)inputs,
                                       (const float4*)centers,
                                       wpc, targets,
                                       (float4*)out_loss,
                                       (float4*)out_tw,
                                       out_centers);
}